// round 1
// baseline (speedup 1.0000x reference)
#include <cuda_runtime.h>
#include <cuda_bf16.h>

// Flash attention (FA2) for [B=2,H=12,S=4096,d=64] fp32, scale = 1/8.
// tf32 mma.sync m16n8k8 with fp32 accumulation, online softmax.
// CTA: 256 threads (8 warps), Br=128 query rows (16 per warp), Bc=64 keys/iter.

#define SEQ     4096
#define DIM     64
#define BH      24
#define BR      128
#define BC      64
#define NTHREAD 256
#define LDS     68   // padded smem row stride (floats): bank = 4*g + tig, conflict-free

__device__ __forceinline__ unsigned f2tf32(float f) {
    unsigned u;
    asm("cvt.rna.tf32.f32 %0, %1;" : "=r"(u) : "f"(f));
    return u;
}

__device__ __forceinline__ void mma_tf32(float c[4], const unsigned a[4],
                                         unsigned b0, unsigned b1) {
    asm volatile(
        "mma.sync.aligned.m16n8k8.row.col.f32.tf32.tf32.f32 "
        "{%0,%1,%2,%3}, {%4,%5,%6,%7}, {%8,%9}, {%0,%1,%2,%3};"
        : "+f"(c[0]), "+f"(c[1]), "+f"(c[2]), "+f"(c[3])
        : "r"(a[0]), "r"(a[1]), "r"(a[2]), "r"(a[3]), "r"(b0), "r"(b1));
}

__global__ __launch_bounds__(NTHREAD)
void fa_tf32_kernel(const float* __restrict__ Q, const float* __restrict__ K,
                    const float* __restrict__ V, float* __restrict__ O)
{
    extern __shared__ float smem[];
    float* Qs = smem;              // BR x LDS ; reused as P after Q frags are in regs
    float* Ks = smem + BR * LDS;   // BC x LDS
    float* Vs = Ks + BC * LDS;     // BC x LDS

    const int tid  = threadIdx.x;
    const int warp = tid >> 5;
    const int lane = tid & 31;
    const int g    = lane >> 2;   // group id (row within fragment)
    const int tig  = lane & 3;    // thread in group (col within fragment)
    const int mrow = warp * 16;   // this warp's query-row base within the tile

    const int qt = blockIdx.x;
    const int bh = blockIdx.y;
    const float* Qg = Q + ((size_t)bh * SEQ + (size_t)qt * BR) * DIM;
    const float* Kg = K + (size_t)bh * SEQ * DIM;
    const float* Vg = V + (size_t)bh * SEQ * DIM;
    float*       Og = O + ((size_t)bh * SEQ + (size_t)qt * BR) * DIM;

    // ---- Load Q tile (pre-scaled by 1/sqrt(d)) ----
    const float scale = 0.125f;
    for (int i = tid; i < BR * (DIM / 4); i += NTHREAD) {
        int r = i >> 4, c = i & 15;
        float4 v = ((const float4*)Qg)[i];
        v.x *= scale; v.y *= scale; v.z *= scale; v.w *= scale;
        *(float4*)(Qs + r * LDS + c * 4) = v;
    }
    __syncthreads();

    // ---- Q fragments in registers (persist across the whole K loop) ----
    unsigned Qa[8][4];
#pragma unroll
    for (int kt = 0; kt < 8; kt++) {
        Qa[kt][0] = f2tf32(Qs[(mrow + g) * LDS + kt * 8 + tig]);
        Qa[kt][1] = f2tf32(Qs[(mrow + g + 8) * LDS + kt * 8 + tig]);
        Qa[kt][2] = f2tf32(Qs[(mrow + g) * LDS + kt * 8 + tig + 4]);
        Qa[kt][3] = f2tf32(Qs[(mrow + g + 8) * LDS + kt * 8 + tig + 4]);
    }

    float Oa[8][4];
#pragma unroll
    for (int nt = 0; nt < 8; nt++)
        Oa[nt][0] = Oa[nt][1] = Oa[nt][2] = Oa[nt][3] = 0.f;
    float m0 = -1e30f, m1 = -1e30f, l0 = 0.f, l1 = 0.f;

    for (int jt = 0; jt < SEQ / BC; jt++) {
        // ---- Load K,V tiles (coalesced float4) ----
        const float4* Kt = (const float4*)(Kg + (size_t)jt * BC * DIM);
        const float4* Vt = (const float4*)(Vg + (size_t)jt * BC * DIM);
        for (int i = tid; i < BC * (DIM / 4); i += NTHREAD) {
            int r = i >> 4, c = i & 15;
            *(float4*)(Ks + r * LDS + c * 4) = Kt[i];
            *(float4*)(Vs + r * LDS + c * 4) = Vt[i];
        }
        __syncthreads();

        // ---- S = (Q*scale) @ K^T : 16x64 per warp ----
        float Sa[8][4];
#pragma unroll
        for (int nt = 0; nt < 8; nt++) {
            Sa[nt][0] = Sa[nt][1] = Sa[nt][2] = Sa[nt][3] = 0.f;
            const float* kr = Ks + (nt * 8 + g) * LDS;
#pragma unroll
            for (int kt = 0; kt < 8; kt++) {
                unsigned b0 = f2tf32(kr[kt * 8 + tig]);
                unsigned b1 = f2tf32(kr[kt * 8 + tig + 4]);
                mma_tf32(Sa[nt], Qa[kt], b0, b1);
            }
        }

        // ---- Online softmax (rows g and g+8 of this warp's 16) ----
        float mt0 = -1e30f, mt1 = -1e30f;
#pragma unroll
        for (int nt = 0; nt < 8; nt++) {
            mt0 = fmaxf(mt0, fmaxf(Sa[nt][0], Sa[nt][1]));
            mt1 = fmaxf(mt1, fmaxf(Sa[nt][2], Sa[nt][3]));
        }
        mt0 = fmaxf(mt0, __shfl_xor_sync(0xffffffffu, mt0, 1));
        mt0 = fmaxf(mt0, __shfl_xor_sync(0xffffffffu, mt0, 2));
        mt1 = fmaxf(mt1, __shfl_xor_sync(0xffffffffu, mt1, 1));
        mt1 = fmaxf(mt1, __shfl_xor_sync(0xffffffffu, mt1, 2));

        float mn0 = fmaxf(m0, mt0), mn1 = fmaxf(m1, mt1);
        float a0 = __expf(m0 - mn0), a1 = __expf(m1 - mn1);
        m0 = mn0; m1 = mn1;

        float rs0 = 0.f, rs1 = 0.f;
#pragma unroll
        for (int nt = 0; nt < 8; nt++) {
            Sa[nt][0] = __expf(Sa[nt][0] - mn0); rs0 += Sa[nt][0];
            Sa[nt][1] = __expf(Sa[nt][1] - mn0); rs0 += Sa[nt][1];
            Sa[nt][2] = __expf(Sa[nt][2] - mn1); rs1 += Sa[nt][2];
            Sa[nt][3] = __expf(Sa[nt][3] - mn1); rs1 += Sa[nt][3];
        }
        rs0 += __shfl_xor_sync(0xffffffffu, rs0, 1);
        rs0 += __shfl_xor_sync(0xffffffffu, rs0, 2);
        rs1 += __shfl_xor_sync(0xffffffffu, rs1, 1);
        rs1 += __shfl_xor_sync(0xffffffffu, rs1, 2);
        l0 = l0 * a0 + rs0;
        l1 = l1 * a1 + rs1;

#pragma unroll
        for (int nt = 0; nt < 8; nt++) {
            Oa[nt][0] *= a0; Oa[nt][1] *= a0;
            Oa[nt][2] *= a1; Oa[nt][3] *= a1;
        }

        // ---- Stage P through smem (warp-private rows of Qs region) ----
        float* Pr0 = Qs + (mrow + g) * LDS;
        float* Pr1 = Qs + (mrow + g + 8) * LDS;
#pragma unroll
        for (int nt = 0; nt < 8; nt++) {
            *(float2*)(Pr0 + nt * 8 + 2 * tig) = make_float2(Sa[nt][0], Sa[nt][1]);
            *(float2*)(Pr1 + nt * 8 + 2 * tig) = make_float2(Sa[nt][2], Sa[nt][3]);
        }
        __syncwarp();

        // ---- O += P @ V ----
#pragma unroll
        for (int kt = 0; kt < 8; kt++) {
            unsigned Pa[4];
            Pa[0] = f2tf32(Pr0[kt * 8 + tig]);
            Pa[1] = f2tf32(Pr1[kt * 8 + tig]);
            Pa[2] = f2tf32(Pr0[kt * 8 + tig + 4]);
            Pa[3] = f2tf32(Pr1[kt * 8 + tig + 4]);
            const float* vr0 = Vs + (kt * 8 + tig) * LDS;
            const float* vr1 = Vs + (kt * 8 + tig + 4) * LDS;
#pragma unroll
            for (int nt = 0; nt < 8; nt++) {
                unsigned b0 = f2tf32(vr0[nt * 8 + g]);
                unsigned b1 = f2tf32(vr1[nt * 8 + g]);
                mma_tf32(Oa[nt], Pa, b0, b1);
            }
        }
        __syncthreads();  // before K/V smem overwrite next iter
    }

    // ---- Normalize and write out ----
    float i0 = 1.f / l0, i1 = 1.f / l1;
#pragma unroll
    for (int nt = 0; nt < 8; nt++) {
        *(float2*)(Og + (mrow + g) * DIM + nt * 8 + 2 * tig) =
            make_float2(Oa[nt][0] * i0, Oa[nt][1] * i0);
        *(float2*)(Og + (mrow + g + 8) * DIM + nt * 8 + 2 * tig) =
            make_float2(Oa[nt][2] * i1, Oa[nt][3] * i1);
    }
}

extern "C" void kernel_launch(void* const* d_in, const int* in_sizes, int n_in,
                              void* d_out, int out_size) {
    const float* Q = (const float*)d_in[0];
    const float* K = (const float*)d_in[1];
    const float* V = (const float*)d_in[2];
    float* O = (float*)d_out;

    const int smem_bytes = (BR + BC + BC) * LDS * (int)sizeof(float);  // ~68 KB
    cudaFuncSetAttribute(fa_tf32_kernel,
                         cudaFuncAttributeMaxDynamicSharedMemorySize, smem_bytes);

    dim3 grid(SEQ / BR, BH);
    fa_tf32_kernel<<<grid, NTHREAD, smem_bytes>>>(Q, K, V, O);
}

// round 2
// speedup vs baseline: 2.6433x; 2.6433x over previous
#include <cuda_runtime.h>
#include <cuda_fp16.h>

// FA2 for [B=2,H=12,S=4096,d=64] fp32 in/out.
// fp16 mma.sync m16n8k16 (fp32 accum) + ldmatrix operands.
// S-accumulator registers reused directly as P A-operand (no smem round-trip).
// CTA: 256 threads / 8 warps, Br=128 (16 rows/warp), Bc=64.

#define SEQ  4096
#define DIM  64
#define BH   24
#define BR   128
#define BC   64
#define NT   256
#define PAD  72   // halves per smem row (144B stride -> ldmatrix conflict-free)

__device__ __forceinline__ unsigned sa(const void* p) {
    return (unsigned)__cvta_generic_to_shared(p);
}
__device__ __forceinline__ float ex2(float x) {
    float y; asm("ex2.approx.ftz.f32 %0, %1;" : "=f"(y) : "f"(x)); return y;
}
__device__ __forceinline__ unsigned packh2(float x, float y) {
    __half2 h = __floats2half2_rn(x, y);
    return *reinterpret_cast<unsigned*>(&h);
}
__device__ __forceinline__ void mma_f16(float c[4], unsigned a0, unsigned a1,
                                        unsigned a2, unsigned a3,
                                        unsigned b0, unsigned b1) {
    asm volatile(
        "mma.sync.aligned.m16n8k16.row.col.f32.f16.f16.f32 "
        "{%0,%1,%2,%3}, {%4,%5,%6,%7}, {%8,%9}, {%0,%1,%2,%3};"
        : "+f"(c[0]), "+f"(c[1]), "+f"(c[2]), "+f"(c[3])
        : "r"(a0), "r"(a1), "r"(a2), "r"(a3), "r"(b0), "r"(b1));
}
__device__ __forceinline__ void ldm4(unsigned r[4], unsigned addr) {
    asm volatile("ldmatrix.sync.aligned.m8n8.x4.shared.b16 {%0,%1,%2,%3}, [%4];"
        : "=r"(r[0]), "=r"(r[1]), "=r"(r[2]), "=r"(r[3]) : "r"(addr));
}
__device__ __forceinline__ void ldm4t(unsigned r[4], unsigned addr) {
    asm volatile("ldmatrix.sync.aligned.m8n8.x4.trans.shared.b16 {%0,%1,%2,%3}, [%4];"
        : "=r"(r[0]), "=r"(r[1]), "=r"(r[2]), "=r"(r[3]) : "r"(addr));
}

__global__ __launch_bounds__(NT, 2)
void fa_f16_kernel(const float* __restrict__ Q, const float* __restrict__ K,
                   const float* __restrict__ V, float* __restrict__ O)
{
    __shared__ __half smem[(BR + 2 * BC) * PAD];
    __half* Qs = smem;
    __half* Ks = smem + BR * PAD;
    __half* Vs = Ks + BC * PAD;

    const int tid  = threadIdx.x;
    const int warp = tid >> 5;
    const int lane = tid & 31;
    const int g    = lane >> 2;
    const int tig  = lane & 3;
    const int quad = lane >> 3;   // ldmatrix: which 8x8 matrix this lane addresses
    const int lr   = lane & 7;    // ldmatrix: row within that matrix
    const int mrow = warp * 16;

    const int qt = blockIdx.x;
    const int bh = blockIdx.y;
    const float* Qg = Q + ((size_t)bh * SEQ + (size_t)qt * BR) * DIM;
    const float* Kg = K + (size_t)bh * SEQ * DIM;
    const float* Vg = V + (size_t)bh * SEQ * DIM;
    float*       Og = O + ((size_t)bh * SEQ + (size_t)qt * BR) * DIM;

    // ---- Load Q tile -> half, pre-scaled by (1/sqrt(d)) * log2(e) ----
    const float qscale = 0.125f * 1.44269504f;
    for (int i = tid; i < BR * (DIM / 4); i += NT) {
        int r = i >> 4, c = i & 15;
        float4 v = ((const float4*)Qg)[i];
        __half* p = Qs + r * PAD + c * 4;
        *(__half2*)(p)     = __floats2half2_rn(v.x * qscale, v.y * qscale);
        *(__half2*)(p + 2) = __floats2half2_rn(v.z * qscale, v.w * qscale);
    }
    __syncthreads();

    // ---- Q fragments (A operand, 4 k16-blocks) ----
    unsigned Qa[4][4];
#pragma unroll
    for (int kt = 0; kt < 4; kt++) {
        int row = mrow + (quad & 1) * 8 + lr;
        int col = kt * 16 + (quad >> 1) * 8;
        ldm4(Qa[kt], sa(Qs + row * PAD + col));
    }
    __syncthreads();  // Q smem no longer needed (not reused, but keep tiles stable)

    float Oa[8][4];
#pragma unroll
    for (int nt = 0; nt < 8; nt++)
        Oa[nt][0] = Oa[nt][1] = Oa[nt][2] = Oa[nt][3] = 0.f;
    float m0 = -1e30f, m1 = -1e30f, l0 = 0.f, l1 = 0.f;

    // ldmatrix lane-address bases (halves offsets added per use)
    const unsigned kbase = sa(Ks + lr * PAD + quad * 8);                       // K: 4 k-chunks, same rows
    const unsigned vbase = sa(Vs + ((quad & 1) * 8 + lr) * PAD + (quad >> 1) * 8); // V: 2x2 blocks

    for (int jt = 0; jt < SEQ / BC; jt++) {
        // ---- Load K,V tiles (fp32 gmem -> half smem) ----
        const float4* Kt = (const float4*)(Kg + (size_t)jt * BC * DIM);
        const float4* Vt = (const float4*)(Vg + (size_t)jt * BC * DIM);
#pragma unroll
        for (int ii = 0; ii < BC * (DIM / 4) / NT; ii++) {
            int i = ii * NT + tid;
            int r = i >> 4, c = i & 15;
            float4 kv = Kt[i];
            __half* pk = Ks + r * PAD + c * 4;
            *(__half2*)(pk)     = __floats2half2_rn(kv.x, kv.y);
            *(__half2*)(pk + 2) = __floats2half2_rn(kv.z, kv.w);
            float4 vv = Vt[i];
            __half* pv = Vs + r * PAD + c * 4;
            *(__half2*)(pv)     = __floats2half2_rn(vv.x, vv.y);
            *(__half2*)(pv + 2) = __floats2half2_rn(vv.z, vv.w);
        }
        __syncthreads();

        // ---- S = Qs @ K^T (log2-scaled), 16x64 per warp ----
        float Sa[8][4];
#pragma unroll
        for (int nt = 0; nt < 8; nt++)
            Sa[nt][0] = Sa[nt][1] = Sa[nt][2] = Sa[nt][3] = 0.f;
#pragma unroll
        for (int ktt = 0; ktt < 2; ktt++) {
#pragma unroll
            for (int nt = 0; nt < 8; nt++) {
                unsigned b[4];
                ldm4(b, kbase + (nt * 8 * PAD + ktt * 32) * 2);
                mma_f16(Sa[nt], Qa[2*ktt][0], Qa[2*ktt][1], Qa[2*ktt][2], Qa[2*ktt][3], b[0], b[1]);
                mma_f16(Sa[nt], Qa[2*ktt+1][0], Qa[2*ktt+1][1], Qa[2*ktt+1][2], Qa[2*ktt+1][3], b[2], b[3]);
            }
        }

        // ---- Online softmax (base-2 domain) ----
        float mt0 = -1e30f, mt1 = -1e30f;
#pragma unroll
        for (int nt = 0; nt < 8; nt++) {
            mt0 = fmaxf(mt0, fmaxf(Sa[nt][0], Sa[nt][1]));
            mt1 = fmaxf(mt1, fmaxf(Sa[nt][2], Sa[nt][3]));
        }
        mt0 = fmaxf(mt0, __shfl_xor_sync(0xffffffffu, mt0, 1));
        mt0 = fmaxf(mt0, __shfl_xor_sync(0xffffffffu, mt0, 2));
        mt1 = fmaxf(mt1, __shfl_xor_sync(0xffffffffu, mt1, 1));
        mt1 = fmaxf(mt1, __shfl_xor_sync(0xffffffffu, mt1, 2));

        float mn0 = fmaxf(m0, mt0), mn1 = fmaxf(m1, mt1);
        float a0 = ex2(m0 - mn0), a1 = ex2(m1 - mn1);
        m0 = mn0; m1 = mn1;

        float rs0 = 0.f, rs1 = 0.f;
#pragma unroll
        for (int nt = 0; nt < 8; nt++) {
            Sa[nt][0] = ex2(Sa[nt][0] - mn0); rs0 += Sa[nt][0];
            Sa[nt][1] = ex2(Sa[nt][1] - mn0); rs0 += Sa[nt][1];
            Sa[nt][2] = ex2(Sa[nt][2] - mn1); rs1 += Sa[nt][2];
            Sa[nt][3] = ex2(Sa[nt][3] - mn1); rs1 += Sa[nt][3];
        }
        rs0 += __shfl_xor_sync(0xffffffffu, rs0, 1);
        rs0 += __shfl_xor_sync(0xffffffffu, rs0, 2);
        rs1 += __shfl_xor_sync(0xffffffffu, rs1, 1);
        rs1 += __shfl_xor_sync(0xffffffffu, rs1, 2);
        l0 = l0 * a0 + rs0;
        l1 = l1 * a1 + rs1;

#pragma unroll
        for (int nt = 0; nt < 8; nt++) {
            Oa[nt][0] *= a0; Oa[nt][1] *= a0;
            Oa[nt][2] *= a1; Oa[nt][3] *= a1;
        }

        // ---- O += P @ V : P straight from S registers ----
#pragma unroll
        for (int kt = 0; kt < 4; kt++) {
            unsigned p0 = packh2(Sa[2*kt][0],   Sa[2*kt][1]);
            unsigned p1 = packh2(Sa[2*kt][2],   Sa[2*kt][3]);
            unsigned p2 = packh2(Sa[2*kt+1][0], Sa[2*kt+1][1]);
            unsigned p3 = packh2(Sa[2*kt+1][2], Sa[2*kt+1][3]);
#pragma unroll
            for (int ntt = 0; ntt < 4; ntt++) {
                unsigned v[4];
                ldm4t(v, vbase + (kt * 16 * PAD + ntt * 16) * 2);
                mma_f16(Oa[2*ntt],   p0, p1, p2, p3, v[0], v[1]);
                mma_f16(Oa[2*ntt+1], p0, p1, p2, p3, v[2], v[3]);
            }
        }
        __syncthreads();  // before K/V overwrite
    }

    // ---- Normalize and store ----
    float i0 = 1.f / l0, i1 = 1.f / l1;
#pragma unroll
    for (int nt = 0; nt < 8; nt++) {
        *(float2*)(Og + (mrow + g) * DIM + nt * 8 + 2 * tig) =
            make_float2(Oa[nt][0] * i0, Oa[nt][1] * i0);
        *(float2*)(Og + (mrow + g + 8) * DIM + nt * 8 + 2 * tig) =
            make_float2(Oa[nt][2] * i1, Oa[nt][3] * i1);
    }
}

extern "C" void kernel_launch(void* const* d_in, const int* in_sizes, int n_in,
                              void* d_out, int out_size) {
    const float* Q = (const float*)d_in[0];
    const float* K = (const float*)d_in[1];
    const float* V = (const float*)d_in[2];
    float* O = (float*)d_out;

    dim3 grid(SEQ / BR, BH);
    fa_f16_kernel<<<grid, NT>>>(Q, K, V, O);
}